// round 5
// baseline (speedup 1.0000x reference)
#include <cuda_runtime.h>
#include <math.h>

#define NP 768
#define DD 128
#define NH 8
#define AA 312

// ---------------- scratch (device globals, no allocation) ----------------
__device__ float g_ve[NP * NP];
__device__ float g_se[NP * NP];
__device__ float g_p [NP * DD];
__device__ float g_t [NP * DD];
__device__ float g_nrm[NP];
__device__ float g_ah[NP * NH];

// ---------------- row L2 norms, 8 rows per block (one warp per row) ----------------
__global__ void rownorm_k(const float* __restrict__ X, int cols, float* __restrict__ out) {
    int row = blockIdx.x * 8 + (threadIdx.x >> 5);
    int lane = threadIdx.x & 31;
    const float* x = X + (size_t)row * cols;
    float s = 0.f;
    for (int c = lane; c < cols; c += 32) { float v = x[c]; s += v * v; }
    #pragma unroll
    for (int o = 16; o; o >>= 1) s += __shfl_down_sync(0xffffffffu, s, o);
    if (lane == 0) out[row] = sqrtf(s);
}

// ---------------- cosine-sim "GEMM": C[i][j] = dot(Xi,Xj)/max(ni*nj,eps)*invtemp --------
__global__ void __launch_bounds__(256, 2)
sim_kernel(const float* __restrict__ X, int K,
           const float* __restrict__ nrm, float invtemp,
           float* __restrict__ C) {
    __shared__ float As[32][34];
    __shared__ float Bs[32][34];
    int i0 = blockIdx.y * 32, j0 = blockIdx.x * 32;
    int tx = threadIdx.x, ty = threadIdx.y;          // 16x16
    int t = ty * 16 + tx;
    float acc[2][2] = {{0.f,0.f},{0.f,0.f}};
    for (int k0 = 0; k0 < K; k0 += 32) {
        #pragma unroll
        for (int e = 0; e < 4; e++) {
            int idx = t + e * 256;
            int r = idx >> 5, c = idx & 31;
            int kk = k0 + c;
            float av = 0.f, bv = 0.f;
            if (kk < K) {
                av = X[(size_t)(i0 + r) * K + kk];
                bv = X[(size_t)(j0 + r) * K + kk];
            }
            As[r][c] = av;
            Bs[r][c] = bv;
        }
        __syncthreads();
        #pragma unroll
        for (int kk = 0; kk < 32; kk += 2) {
            float2 a0 = *(const float2*)&As[ty][kk];
            float2 a1 = *(const float2*)&As[ty + 16][kk];
            float2 b0 = *(const float2*)&Bs[tx][kk];
            float2 b1 = *(const float2*)&Bs[tx + 16][kk];
            acc[0][0] += a0.x * b0.x + a0.y * b0.y;
            acc[0][1] += a0.x * b1.x + a0.y * b1.y;
            acc[1][0] += a1.x * b0.x + a1.y * b0.y;
            acc[1][1] += a1.x * b1.x + a1.y * b1.y;
        }
        __syncthreads();
    }
    #pragma unroll
    for (int a = 0; a < 2; a++) {
        int i = i0 + ty + a * 16;
        float ni = nrm[i];
        #pragma unroll
        for (int b = 0; b < 2; b++) {
            int j = j0 + tx + b * 16;
            float den = fmaxf(ni * nrm[j], 1e-8f);
            C[(size_t)i * NP + j] = acc[a][b] / den * invtemp;
        }
    }
}

// ---------------- row softmax, in place, row length NP ----------------
__global__ void softmax_kernel(float* __restrict__ M) {
    __shared__ float buf[NP];
    __shared__ float red[8];
    int row = blockIdx.x;
    float* p = M + (size_t)row * NP;
    int t = threadIdx.x;                     // 256
    int wid = t >> 5, lane = t & 31;
    float mx = -1e30f;
    for (int c = t; c < NP; c += 256) { float v = p[c]; buf[c] = v; mx = fmaxf(mx, v); }
    #pragma unroll
    for (int o = 16; o; o >>= 1) mx = fmaxf(mx, __shfl_down_sync(0xffffffffu, mx, o));
    if (lane == 0) red[wid] = mx;
    __syncthreads();
    mx = red[0];
    #pragma unroll
    for (int w = 1; w < 8; w++) mx = fmaxf(mx, red[w]);
    float sum = 0.f;
    for (int c = t; c < NP; c += 256) { float e = expf(buf[c] - mx); buf[c] = e; sum += e; }
    __syncthreads();
    #pragma unroll
    for (int o = 16; o; o >>= 1) sum += __shfl_down_sync(0xffffffffu, sum, o);
    if (lane == 0) red[wid] = sum;
    __syncthreads();
    sum = 0.f;
    #pragma unroll
    for (int w = 0; w < 8; w++) sum += red[w];
    float inv = 1.f / sum;
    for (int c = t; c < NP; c += 256) p[c] = buf[c] * inv;
}

// ---------------- dual aggregation: p = edge@proto ; t = (edge+last)@proto ----------------
__global__ void __launch_bounds__(256, 2)
dualagg_kernel(const float* __restrict__ edge, const float* __restrict__ last,
               const float* __restrict__ proto,
               float* __restrict__ outp, float* __restrict__ outt) {
    __shared__ float E1[32][34];
    __shared__ float E2[32][34];
    __shared__ float Pr[32][34];
    int i0 = blockIdx.y * 32, d0 = blockIdx.x * 32;
    int tx = threadIdx.x, ty = threadIdx.y;
    int t = ty * 16 + tx;
    float ap[2][2] = {{0.f,0.f},{0.f,0.f}};
    float at[2][2] = {{0.f,0.f},{0.f,0.f}};
    for (int k0 = 0; k0 < NP; k0 += 32) {
        #pragma unroll
        for (int e = 0; e < 4; e++) {
            int idx = t + e * 256;
            int r = idx >> 5, c = idx & 31;
            E1[r][c] = edge[(size_t)(i0 + r) * NP + k0 + c];
            E2[r][c] = last[(size_t)(i0 + r) * NP + k0 + c];
            Pr[r][c] = proto[(size_t)(k0 + r) * DD + d0 + c];
        }
        __syncthreads();
        #pragma unroll
        for (int kk = 0; kk < 32; kk += 2) {
            float2 e10 = *(const float2*)&E1[ty][kk];
            float2 e11 = *(const float2*)&E1[ty + 16][kk];
            float2 f0  = *(const float2*)&E2[ty][kk];
            float2 f1  = *(const float2*)&E2[ty + 16][kk];
            float s0x = e10.x + f0.x, s0y = e10.y + f0.y;
            float s1x = e11.x + f1.x, s1y = e11.y + f1.y;
            float p0x = Pr[kk][tx],     p1x = Pr[kk][tx + 16];
            float p0y = Pr[kk + 1][tx], p1y = Pr[kk + 1][tx + 16];
            ap[0][0] += e10.x * p0x + e10.y * p0y;
            ap[0][1] += e10.x * p1x + e10.y * p1y;
            ap[1][0] += e11.x * p0x + e11.y * p0y;
            ap[1][1] += e11.x * p1x + e11.y * p1y;
            at[0][0] += s0x * p0x + s0y * p0y;
            at[0][1] += s0x * p1x + s0y * p1y;
            at[1][0] += s1x * p0x + s1y * p0y;
            at[1][1] += s1x * p1x + s1y * p1y;
        }
        __syncthreads();
    }
    #pragma unroll
    for (int a = 0; a < 2; a++) {
        int i = i0 + ty + a * 16;
        #pragma unroll
        for (int b = 0; b < 2; b++) {
            int d = d0 + tx + b * 16;
            outp[(size_t)i * DD + d] = ap[a][b];
            outt[(size_t)i * DD + d] = at[a][b];
        }
    }
}

// --- out = relu(LN(t@W^T + b)*g + beta) + p ; fused A[i][h] = sum_d W1[h,d]*out^2 ------
__global__ void linear_ln_kernel(const float* __restrict__ T, const float* __restrict__ P,
                                 const float* __restrict__ W, const float* __restrict__ bias,
                                 const float* __restrict__ gamma, const float* __restrict__ beta,
                                 const float* __restrict__ W1, float* __restrict__ A,
                                 float* __restrict__ out) {
    __shared__ float trow[DD];
    __shared__ float x2s[DD];
    __shared__ float red[4];
    int i = blockIdx.x, d = threadIdx.x;     // 128 threads = 4 warps
    int wid = d >> 5, lane = d & 31;
    trow[d] = T[(size_t)i * DD + d];
    __syncthreads();
    const float* w = W + (size_t)d * DD;
    float acc = bias[d];
    #pragma unroll 8
    for (int k = 0; k < DD; k++) acc += trow[k] * w[k];
    // mean
    float s = acc;
    #pragma unroll
    for (int o = 16; o; o >>= 1) s += __shfl_down_sync(0xffffffffu, s, o);
    if (lane == 0) red[wid] = s;
    __syncthreads();
    float m = (red[0] + red[1] + red[2] + red[3]) * (1.f / DD);
    __syncthreads();
    float dev = acc - m;
    float v = dev * dev;
    #pragma unroll
    for (int o = 16; o; o >>= 1) v += __shfl_down_sync(0xffffffffu, v, o);
    if (lane == 0) red[wid] = v;
    __syncthreads();
    float var = (red[0] + red[1] + red[2] + red[3]) * (1.f / DD);
    float y = dev * rsqrtf(var + 1e-5f) * gamma[d] + beta[d];
    float o_val = fmaxf(y, 0.f) + P[(size_t)i * DD + d];
    out[(size_t)i * DD + d] = o_val;
    // fused ah: A[i][h] = sum_d W1[h][d] * o_val^2  (warp w handles h=2w, 2w+1)
    x2s[d] = o_val * o_val;
    __syncthreads();
    #pragma unroll
    for (int hh = 0; hh < 2; hh++) {
        int h = wid * 2 + hh;
        float sa = 0.f;
        #pragma unroll
        for (int q = 0; q < 4; q++) {
            int dd = lane + q * 32;
            sa += W1[h * DD + dd] * x2s[dd];
        }
        #pragma unroll
        for (int o = 16; o; o >>= 1) sa += __shfl_down_sync(0xffffffffu, sa, o);
        if (lane == 0) A[i * NH + h] = sa;
    }
}

// ---------------- fused edge-MLP, 32(i) x 64(j) tile, 2x4 per thread ----------------
__global__ void __launch_bounds__(256)
edge_kernel(const float* __restrict__ Pm, const float* __restrict__ A,
            const float* __restrict__ W1, const float* __restrict__ b1,
            const float* __restrict__ W2, const float* __restrict__ b2,
            const float* __restrict__ last, float invtemp,
            float* __restrict__ out) {
    __shared__ float Pi[32][34];
    __shared__ float Pj[64][34];
    __shared__ float Ws[NH][34];
    int i0 = blockIdx.y * 32, j0 = blockIdx.x * 64;
    int tx = threadIdx.x, ty = threadIdx.y;   // 16x16
    int t = ty * 16 + tx;
    float c[2][4][NH];
    #pragma unroll
    for (int a = 0; a < 2; a++)
        #pragma unroll
        for (int b = 0; b < 4; b++)
            #pragma unroll
            for (int h = 0; h < NH; h++) c[a][b][h] = 0.f;
    for (int k0 = 0; k0 < DD; k0 += 32) {
        #pragma unroll
        for (int e = 0; e < 4; e++) {
            int idx = t + e * 256;
            int r = idx >> 5, cc = idx & 31;
            Pi[r][cc] = Pm[(size_t)(i0 + r) * DD + k0 + cc];
        }
        #pragma unroll
        for (int e = 0; e < 8; e++) {
            int idx = t + e * 256;
            int r = idx >> 5, cc = idx & 31;
            Pj[r][cc] = Pm[(size_t)(j0 + r) * DD + k0 + cc];
        }
        Ws[t >> 5][t & 31] = W1[(t >> 5) * DD + k0 + (t & 31)];  // 256 = NH*32
        __syncthreads();
        #pragma unroll
        for (int kk = 0; kk < 32; kk += 2) {
            float2 piv[2], pjv[4], wv[NH];
            piv[0] = *(const float2*)&Pi[ty][kk];
            piv[1] = *(const float2*)&Pi[ty + 16][kk];
            #pragma unroll
            for (int b = 0; b < 4; b++) pjv[b] = *(const float2*)&Pj[tx + 16 * b][kk];
            #pragma unroll
            for (int h = 0; h < NH; h++) wv[h] = *(const float2*)&Ws[h][kk];
            #pragma unroll
            for (int a = 0; a < 2; a++) {
                #pragma unroll
                for (int b = 0; b < 4; b++) {
                    float px = piv[a].x * pjv[b].x;
                    float py = piv[a].y * pjv[b].y;
                    #pragma unroll
                    for (int h = 0; h < NH; h++)
                        c[a][b][h] += wv[h].x * px + wv[h].y * py;
                }
            }
        }
        __syncthreads();
    }
    float w2[NH], bb1[NH];
    #pragma unroll
    for (int h = 0; h < NH; h++) { w2[h] = W2[h]; bb1[h] = b1[h]; }
    float bb2 = b2[0];
    float Ai[2][NH], Aj[4][NH];
    #pragma unroll
    for (int h = 0; h < NH; h++) {
        Ai[0][h] = A[(i0 + ty) * NH + h];
        Ai[1][h] = A[(i0 + ty + 16) * NH + h];
        #pragma unroll
        for (int b = 0; b < 4; b++)
            Aj[b][h] = A[(j0 + tx + 16 * b) * NH + h];
    }
    #pragma unroll
    for (int a = 0; a < 2; a++) {
        int i = i0 + ty + a * 16;
        #pragma unroll
        for (int b = 0; b < 4; b++) {
            int j = j0 + tx + b * 16;
            float hr[NH];
            float m = 0.f;
            #pragma unroll
            for (int h = 0; h < NH; h++) {
                hr[h] = Ai[a][h] + Aj[b][h] + bb1[h] - 2.f * c[a][b][h];
                m += hr[h];
            }
            m *= (1.f / NH);
            float v = 0.f;
            #pragma unroll
            for (int h = 0; h < NH; h++) { float dd = hr[h] - m; v += dd * dd; }
            v *= (1.f / NH);
            float inv = rsqrtf(v + 1e-5f);
            float acc = bb2;
            #pragma unroll
            for (int h = 0; h < NH; h++) {
                float hn = (hr[h] - m) * inv;
                hn = fmaxf(hn, 0.f);
                acc += hn * w2[h];
            }
            float e = tanhf(acc);
            out[(size_t)i * NP + j] = e * (last[(size_t)i * NP + j] + 1e-8f) * invtemp;
        }
    }
}

// =========================================================================================
extern "C" void kernel_launch(void* const* d_in, const int* in_sizes, int n_in,
                              void* d_out, int out_size) {
    const float* visual   = (const float*)d_in[0];
    const float* semantic = (const float*)d_in[1];
    const float* attrib   = (const float*)d_in[2];
    const float* Wvn  = (const float*)d_in[3];
    const float* bvn  = (const float*)d_in[4];
    const float* gvn  = (const float*)d_in[5];
    const float* betavn = (const float*)d_in[6];
    const float* Wve1 = (const float*)d_in[7];
    const float* bve1 = (const float*)d_in[8];
    const float* Wve2 = (const float*)d_in[9];
    const float* bve2 = (const float*)d_in[10];
    const float* Wsn  = (const float*)d_in[11];
    const float* bsn  = (const float*)d_in[12];
    const float* gsn  = (const float*)d_in[13];
    const float* betasn = (const float*)d_in[14];
    const float* Wse1 = (const float*)d_in[15];
    const float* bse1 = (const float*)d_in[16];
    const float* Wse2 = (const float*)d_in[17];
    const float* bse2 = (const float*)d_in[18];

    float* out = (float*)d_out;
    float* vp  = out;
    float* sp  = out + NP * DD;
    float* ve2 = out + 2 * NP * DD;
    float* se2 = ve2 + NP * NP;

    float *ve, *se, *gp, *gt, *gn, *ga;
    cudaGetSymbolAddress((void**)&ve, g_ve);
    cudaGetSymbolAddress((void**)&se, g_se);
    cudaGetSymbolAddress((void**)&gp, g_p);
    cudaGetSymbolAddress((void**)&gt, g_t);
    cudaGetSymbolAddress((void**)&gn, g_nrm);
    cudaGetSymbolAddress((void**)&ga, g_ah);

    dim3 b16(16, 16);
    dim3 gNN(NP / 32, NP / 32);   // 24x24
    dim3 gE (NP / 64, NP / 32);   // 12x24
    dim3 gND(DD / 32, NP / 32);   // 4x24

    // ve = softmax(cos_sim(visual)/0.1)
    rownorm_k<<<NP / 8, 256>>>(visual, DD, gn);
    sim_kernel<<<gNN, b16>>>(visual, DD, gn, 10.f, ve);
    softmax_kernel<<<NP, 256>>>(ve);

    // se = softmax(cos_sim(attribute)/0.1)
    rownorm_k<<<NP / 8, 256>>>(attrib, AA, gn);
    sim_kernel<<<gNN, b16>>>(attrib, AA, gn, 10.f, se);
    softmax_kernel<<<NP, 256>>>(se);

    // vp = node_update(visual, last=se, edge=ve)   [+ fused ah for ve2]
    dualagg_kernel<<<gND, b16>>>(ve, se, visual, gp, gt);
    linear_ln_kernel<<<NP, DD>>>(gt, gp, Wvn, bvn, gvn, betavn, Wve1, ga, vp);

    // ve2 = edge_update(vp, last=ve, temp=10)
    edge_kernel<<<gE, b16>>>(vp, ga, Wve1, bve1, Wve2, bve2, ve, 0.1f, ve2);
    softmax_kernel<<<NP, 256>>>(ve2);

    // sp = node_update(semantic, last=ve2, edge=se)   [+ fused ah for se2]
    dualagg_kernel<<<gND, b16>>>(se, ve2, semantic, gp, gt);
    linear_ln_kernel<<<NP, DD>>>(gt, gp, Wsn, bsn, gsn, betasn, Wse1, ga, sp);

    // se2 = edge_update(sp, last=se, temp=10)
    edge_kernel<<<gE, b16>>>(sp, ga, Wse1, bse1, Wse2, bse2, se, 0.1f, se2);
    softmax_kernel<<<NP, 256>>>(se2);
}

// round 7
// speedup vs baseline: 1.1102x; 1.1102x over previous
#include <cuda_runtime.h>
#include <math.h>

#define NP 768
#define DD 128
#define NH 8
#define AA 312

typedef unsigned long long u64;

// ---------------- f32x2 packed helpers (B300 FFMA2 path, PTX-only) ----------------
__device__ __forceinline__ u64 ffma2(u64 a, u64 b, u64 c) {
    u64 d; asm("fma.rn.f32x2 %0, %1, %2, %3;" : "=l"(d) : "l"(a), "l"(b), "l"(c)); return d;
}
__device__ __forceinline__ u64 fmul2(u64 a, u64 b) {
    u64 d; asm("mul.rn.f32x2 %0, %1, %2;" : "=l"(d) : "l"(a), "l"(b)); return d;
}
__device__ __forceinline__ u64 fadd2(u64 a, u64 b) {
    u64 d; asm("add.rn.f32x2 %0, %1, %2;" : "=l"(d) : "l"(a), "l"(b)); return d;
}
__device__ __forceinline__ float hsum2(u64 v) {
    float x, y; asm("mov.b64 {%0,%1}, %2;" : "=f"(x), "=f"(y) : "l"(v)); return x + y;
}

// ---------------- scratch (device globals, no allocation) ----------------
__device__ float g_ve[NP * NP];
__device__ float g_se[NP * NP];
__device__ float g_p [NP * DD];
__device__ float g_t [NP * DD];
__device__ float g_nrm[2 * NP];
__device__ float g_ah[NP * NH];

// ------------- row L2 norms for BOTH modalities, 8 rows/block -------------
__global__ void rownorm_both_k(const float* __restrict__ V, const float* __restrict__ Aat,
                               float* __restrict__ out) {
    int gr = blockIdx.x * 8 + (threadIdx.x >> 5);   // 0..1535
    int lane = threadIdx.x & 31;
    const float* x; int cols;
    if (gr < NP) { x = V + (size_t)gr * DD; cols = DD; }
    else         { x = Aat + (size_t)(gr - NP) * AA; cols = AA; }
    float s = 0.f;
    for (int c = lane; c < cols; c += 32) { float v = x[c]; s += v * v; }
    #pragma unroll
    for (int o = 16; o; o >>= 1) s += __shfl_down_sync(0xffffffffu, s, o);
    if (lane == 0) out[gr] = sqrtf(s);
}

// ------ cosine-sim GEMMs for BOTH modalities in one launch (z picks modality) ------
__global__ void __launch_bounds__(256, 2)
sim_both_kernel(const float* __restrict__ V, const float* __restrict__ Aat,
                const float* __restrict__ nrm,
                float* __restrict__ CV, float* __restrict__ CS, float invtemp) {
    __shared__ float As[32][34];
    __shared__ float Bs[32][34];
    const float* X; int K; const float* nr; float* C;
    if (blockIdx.z == 0) { X = V;  K = DD; nr = nrm;       C = CV; }
    else                 { X = Aat; K = AA; nr = nrm + NP; C = CS; }
    int i0 = blockIdx.y * 32, j0 = blockIdx.x * 32;
    int tx = threadIdx.x, ty = threadIdx.y;          // 16x16
    int t = ty * 16 + tx;
    u64 acc[2][2] = {{0ull,0ull},{0ull,0ull}};
    for (int k0 = 0; k0 < K; k0 += 32) {
        #pragma unroll
        for (int e = 0; e < 4; e++) {
            int idx = t + e * 256;
            int r = idx >> 5, c = idx & 31;
            int kk = k0 + c;
            float av = 0.f, bv = 0.f;
            if (kk < K) {
                av = X[(size_t)(i0 + r) * K + kk];
                bv = X[(size_t)(j0 + r) * K + kk];
            }
            As[r][c] = av;
            Bs[r][c] = bv;
        }
        __syncthreads();
        #pragma unroll
        for (int kk = 0; kk < 32; kk += 2) {
            u64 a0 = *(const u64*)&As[ty][kk];
            u64 a1 = *(const u64*)&As[ty + 16][kk];
            u64 b0 = *(const u64*)&Bs[tx][kk];
            u64 b1 = *(const u64*)&Bs[tx + 16][kk];
            acc[0][0] = ffma2(a0, b0, acc[0][0]);
            acc[0][1] = ffma2(a0, b1, acc[0][1]);
            acc[1][0] = ffma2(a1, b0, acc[1][0]);
            acc[1][1] = ffma2(a1, b1, acc[1][1]);
        }
        __syncthreads();
    }
    #pragma unroll
    for (int a = 0; a < 2; a++) {
        int i = i0 + ty + a * 16;
        float ni = nr[i];
        #pragma unroll
        for (int b = 0; b < 2; b++) {
            int j = j0 + tx + b * 16;
            float den = fmaxf(ni * nr[j], 1e-8f);
            C[(size_t)i * NP + j] = hsum2(acc[a][b]) / den * invtemp;
        }
    }
}

// ---------------- row softmax, in place; handles one or two matrices ----------------
__global__ void softmax_kernel(float* __restrict__ M1, float* __restrict__ M2) {
    __shared__ float buf[NP];
    __shared__ float red[8];
    int row = blockIdx.x;
    float* p = (row < NP) ? (M1 + (size_t)row * NP) : (M2 + (size_t)(row - NP) * NP);
    int t = threadIdx.x;                     // 256
    int wid = t >> 5, lane = t & 31;
    float mx = -1e30f;
    for (int c = t; c < NP; c += 256) { float v = p[c]; buf[c] = v; mx = fmaxf(mx, v); }
    #pragma unroll
    for (int o = 16; o; o >>= 1) mx = fmaxf(mx, __shfl_down_sync(0xffffffffu, mx, o));
    if (lane == 0) red[wid] = mx;
    __syncthreads();
    mx = red[0];
    #pragma unroll
    for (int w = 1; w < 8; w++) mx = fmaxf(mx, red[w]);
    float sum = 0.f;
    for (int c = t; c < NP; c += 256) { float e = expf(buf[c] - mx); buf[c] = e; sum += e; }
    __syncthreads();
    #pragma unroll
    for (int o = 16; o; o >>= 1) sum += __shfl_down_sync(0xffffffffu, sum, o);
    if (lane == 0) red[wid] = sum;
    __syncthreads();
    sum = 0.f;
    #pragma unroll
    for (int w = 0; w < 8; w++) sum += red[w];
    float inv = 1.f / sum;
    for (int c = t; c < NP; c += 256) p[c] = buf[c] * inv;
}

// ---------------- dual aggregation: p = edge@proto ; t = (edge+last)@proto ----------------
__global__ void __launch_bounds__(256, 2)
dualagg_kernel(const float* __restrict__ edge, const float* __restrict__ last,
               const float* __restrict__ proto,
               float* __restrict__ outp, float* __restrict__ outt) {
    __shared__ float E1[32][34];
    __shared__ float E2[32][34];
    __shared__ float Prt[32][34];          // transposed: [d][k]
    int i0 = blockIdx.y * 32, d0 = blockIdx.x * 32;
    int tx = threadIdx.x, ty = threadIdx.y;
    int t = ty * 16 + tx;
    u64 ap[2][2] = {{0ull,0ull},{0ull,0ull}};
    u64 at[2][2] = {{0ull,0ull},{0ull,0ull}};
    for (int k0 = 0; k0 < NP; k0 += 32) {
        #pragma unroll
        for (int e = 0; e < 4; e++) {
            int idx = t + e * 256;
            int r = idx >> 5, c = idx & 31;
            E1[r][c] = edge[(size_t)(i0 + r) * NP + k0 + c];
            E2[r][c] = last[(size_t)(i0 + r) * NP + k0 + c];
            Prt[c][r] = proto[(size_t)(k0 + r) * DD + d0 + c];
        }
        __syncthreads();
        #pragma unroll
        for (int kk = 0; kk < 32; kk += 2) {
            u64 e10 = *(const u64*)&E1[ty][kk];
            u64 e11 = *(const u64*)&E1[ty + 16][kk];
            u64 f0  = *(const u64*)&E2[ty][kk];
            u64 f1  = *(const u64*)&E2[ty + 16][kk];
            u64 s0 = fadd2(e10, f0);
            u64 s1 = fadd2(e11, f1);
            u64 p0 = *(const u64*)&Prt[tx][kk];
            u64 p1 = *(const u64*)&Prt[tx + 16][kk];
            ap[0][0] = ffma2(e10, p0, ap[0][0]);
            ap[0][1] = ffma2(e10, p1, ap[0][1]);
            ap[1][0] = ffma2(e11, p0, ap[1][0]);
            ap[1][1] = ffma2(e11, p1, ap[1][1]);
            at[0][0] = ffma2(s0, p0, at[0][0]);
            at[0][1] = ffma2(s0, p1, at[0][1]);
            at[1][0] = ffma2(s1, p0, at[1][0]);
            at[1][1] = ffma2(s1, p1, at[1][1]);
        }
        __syncthreads();
    }
    #pragma unroll
    for (int a = 0; a < 2; a++) {
        int i = i0 + ty + a * 16;
        #pragma unroll
        for (int b = 0; b < 2; b++) {
            int d = d0 + tx + b * 16;
            outp[(size_t)i * DD + d] = hsum2(ap[a][b]);
            outt[(size_t)i * DD + d] = hsum2(at[a][b]);
        }
    }
}

// --- out = relu(LN(t@W^T + b)*g + beta) + p ; fused A[i][h] = sum_d W1[h,d]*out^2 ------
__global__ void linear_ln_kernel(const float* __restrict__ T, const float* __restrict__ P,
                                 const float* __restrict__ W, const float* __restrict__ bias,
                                 const float* __restrict__ gamma, const float* __restrict__ beta,
                                 const float* __restrict__ W1, float* __restrict__ A,
                                 float* __restrict__ out) {
    __shared__ float trow[DD];
    __shared__ float x2s[DD];
    __shared__ float red[4];
    int i = blockIdx.x, d = threadIdx.x;     // 128 threads = 4 warps
    int wid = d >> 5, lane = d & 31;
    trow[d] = T[(size_t)i * DD + d];
    __syncthreads();
    const float* w = W + (size_t)d * DD;
    float acc = bias[d];
    #pragma unroll 8
    for (int k = 0; k < DD; k++) acc += trow[k] * w[k];
    float s = acc;
    #pragma unroll
    for (int o = 16; o; o >>= 1) s += __shfl_down_sync(0xffffffffu, s, o);
    if (lane == 0) red[wid] = s;
    __syncthreads();
    float m = (red[0] + red[1] + red[2] + red[3]) * (1.f / DD);
    __syncthreads();
    float dev = acc - m;
    float v = dev * dev;
    #pragma unroll
    for (int o = 16; o; o >>= 1) v += __shfl_down_sync(0xffffffffu, v, o);
    if (lane == 0) red[wid] = v;
    __syncthreads();
    float var = (red[0] + red[1] + red[2] + red[3]) * (1.f / DD);
    float y = dev * rsqrtf(var + 1e-5f) * gamma[d] + beta[d];
    float o_val = fmaxf(y, 0.f) + P[(size_t)i * DD + d];
    out[(size_t)i * DD + d] = o_val;
    x2s[d] = o_val * o_val;
    __syncthreads();
    #pragma unroll
    for (int hh = 0; hh < 2; hh++) {
        int h = wid * 2 + hh;
        float sa = 0.f;
        #pragma unroll
        for (int q = 0; q < 4; q++) {
            int dd = lane + q * 32;
            sa += W1[h * DD + dd] * x2s[dd];
        }
        #pragma unroll
        for (int o = 16; o; o >>= 1) sa += __shfl_down_sync(0xffffffffu, sa, o);
        if (lane == 0) A[i * NH + h] = sa;
    }
}

// ---------------- fused edge-MLP, 32x32 tile, 2x2/thread, f32x2 math ----------------
__global__ void __launch_bounds__(256, 2)
edge_kernel(const float* __restrict__ Pm, const float* __restrict__ A,
            const float* __restrict__ W1, const float* __restrict__ b1,
            const float* __restrict__ W2, const float* __restrict__ b2,
            const float* __restrict__ last, float invtemp,
            float* __restrict__ out) {
    __shared__ float Pi[32][34];
    __shared__ float Pj[32][34];
    __shared__ float Ws[NH][34];
    int i0 = blockIdx.y * 32, j0 = blockIdx.x * 32;
    int tx = threadIdx.x, ty = threadIdx.y;   // 16x16
    int t = ty * 16 + tx;
    u64 c2[2][2][NH];
    #pragma unroll
    for (int a = 0; a < 2; a++)
        #pragma unroll
        for (int b = 0; b < 2; b++)
            #pragma unroll
            for (int h = 0; h < NH; h++) c2[a][b][h] = 0ull;
    for (int k0 = 0; k0 < DD; k0 += 32) {
        #pragma unroll
        for (int e = 0; e < 4; e++) {
            int idx = t + e * 256;
            int r = idx >> 5, cc = idx & 31;
            Pi[r][cc] = Pm[(size_t)(i0 + r) * DD + k0 + cc];
            Pj[r][cc] = Pm[(size_t)(j0 + r) * DD + k0 + cc];
        }
        Ws[t >> 5][t & 31] = W1[(t >> 5) * DD + k0 + (t & 31)];  // 256 = NH*32
        __syncthreads();
        #pragma unroll
        for (int kk = 0; kk < 32; kk += 2) {
            u64 pi0 = *(const u64*)&Pi[ty][kk];
            u64 pi1 = *(const u64*)&Pi[ty + 16][kk];
            u64 pj0 = *(const u64*)&Pj[tx][kk];
            u64 pj1 = *(const u64*)&Pj[tx + 16][kk];
            u64 wv[NH];
            #pragma unroll
            for (int h = 0; h < NH; h++) wv[h] = *(const u64*)&Ws[h][kk];
            u64 p00 = fmul2(pi0, pj0);
            u64 p01 = fmul2(pi0, pj1);
            u64 p10 = fmul2(pi1, pj0);
            u64 p11 = fmul2(pi1, pj1);
            #pragma unroll
            for (int h = 0; h < NH; h++) {
                c2[0][0][h] = ffma2(wv[h], p00, c2[0][0][h]);
                c2[0][1][h] = ffma2(wv[h], p01, c2[0][1][h]);
                c2[1][0][h] = ffma2(wv[h], p10, c2[1][0][h]);
                c2[1][1][h] = ffma2(wv[h], p11, c2[1][1][h]);
            }
        }
        __syncthreads();
    }
    float w2[NH], bb1[NH];
    #pragma unroll
    for (int h = 0; h < NH; h++) { w2[h] = W2[h]; bb1[h] = b1[h]; }
    float bb2 = b2[0];
    float Ai[2][NH], Aj[2][NH];
    #pragma unroll
    for (int h = 0; h < NH; h++) {
        Ai[0][h] = A[(i0 + ty) * NH + h];
        Ai[1][h] = A[(i0 + ty + 16) * NH + h];
        Aj[0][h] = A[(j0 + tx) * NH + h];
        Aj[1][h] = A[(j0 + tx + 16) * NH + h];
    }
    #pragma unroll
    for (int a = 0; a < 2; a++) {
        int i = i0 + ty + a * 16;
        #pragma unroll
        for (int b = 0; b < 2; b++) {
            int j = j0 + tx + b * 16;
            float hr[NH];
            float m = 0.f;
            #pragma unroll
            for (int h = 0; h < NH; h++) {
                hr[h] = Ai[a][h] + Aj[b][h] + bb1[h] - 2.f * hsum2(c2[a][b][h]);
                m += hr[h];
            }
            m *= (1.f / NH);
            float v = 0.f;
            #pragma unroll
            for (int h = 0; h < NH; h++) { float dd = hr[h] - m; v += dd * dd; }
            v *= (1.f / NH);
            float inv = rsqrtf(v + 1e-5f);
            float acc = bb2;
            #pragma unroll
            for (int h = 0; h < NH; h++) {
                float hn = (hr[h] - m) * inv;
                hn = fmaxf(hn, 0.f);
                acc += hn * w2[h];
            }
            float e = tanhf(acc);
            out[(size_t)i * NP + j] = e * (last[(size_t)i * NP + j] + 1e-8f) * invtemp;
        }
    }
}

// =========================================================================================
extern "C" void kernel_launch(void* const* d_in, const int* in_sizes, int n_in,
                              void* d_out, int out_size) {
    const float* visual   = (const float*)d_in[0];
    const float* semantic = (const float*)d_in[1];
    const float* attrib   = (const float*)d_in[2];
    const float* Wvn  = (const float*)d_in[3];
    const float* bvn  = (const float*)d_in[4];
    const float* gvn  = (const float*)d_in[5];
    const float* betavn = (const float*)d_in[6];
    const float* Wve1 = (const float*)d_in[7];
    const float* bve1 = (const float*)d_in[8];
    const float* Wve2 = (const float*)d_in[9];
    const float* bve2 = (const float*)d_in[10];
    const float* Wsn  = (const float*)d_in[11];
    const float* bsn  = (const float*)d_in[12];
    const float* gsn  = (const float*)d_in[13];
    const float* betasn = (const float*)d_in[14];
    const float* Wse1 = (const float*)d_in[15];
    const float* bse1 = (const float*)d_in[16];
    const float* Wse2 = (const float*)d_in[17];
    const float* bse2 = (const float*)d_in[18];

    float* out = (float*)d_out;
    float* vp  = out;
    float* sp  = out + NP * DD;
    float* ve2 = out + 2 * NP * DD;
    float* se2 = ve2 + NP * NP;

    float *ve, *se, *gp, *gt, *gn, *ga;
    cudaGetSymbolAddress((void**)&ve, g_ve);
    cudaGetSymbolAddress((void**)&se, g_se);
    cudaGetSymbolAddress((void**)&gp, g_p);
    cudaGetSymbolAddress((void**)&gt, g_t);
    cudaGetSymbolAddress((void**)&gn, g_nrm);
    cudaGetSymbolAddress((void**)&ga, g_ah);

    dim3 b16(16, 16);
    dim3 gNN(NP / 32, NP / 32);        // 24x24
    dim3 gSim(NP / 32, NP / 32, 2);    // both modalities
    dim3 gND(DD / 32, NP / 32);        // 4x24

    // ve, se = softmax(cos_sim(...)/0.1) — both modalities batched per launch
    rownorm_both_k<<<2 * NP / 8, 256>>>(visual, attrib, gn);
    sim_both_kernel<<<gSim, b16>>>(visual, attrib, gn, ve, se, 10.f);
    softmax_kernel<<<2 * NP, 256>>>(ve, se);

    // vp = node_update(visual, last=se, edge=ve)   [+ fused ah for ve2]
    dualagg_kernel<<<gND, b16>>>(ve, se, visual, gp, gt);
    linear_ln_kernel<<<NP, DD>>>(gt, gp, Wvn, bvn, gvn, betavn, Wve1, ga, vp);

    // ve2 = edge_update(vp, last=ve, temp=10)
    edge_kernel<<<gNN, b16>>>(vp, ga, Wve1, bve1, Wve2, bve2, ve, 0.1f, ve2);
    softmax_kernel<<<NP, 256>>>(ve2, ve2);

    // sp = node_update(semantic, last=ve2, edge=se)   [+ fused ah for se2]
    dualagg_kernel<<<gND, b16>>>(se, ve2, semantic, gp, gt);
    linear_ln_kernel<<<NP, DD>>>(gt, gp, Wsn, bsn, gsn, betasn, Wse1, ga, sp);

    // se2 = edge_update(sp, last=se, temp=10)
    edge_kernel<<<gNN, b16>>>(sp, ga, Wse1, bse1, Wse2, bse2, se, 0.1f, se2);
    softmax_kernel<<<NP, 256>>>(se2, se2);
}

// round 8
// speedup vs baseline: 1.2217x; 1.1004x over previous
#include <cuda_runtime.h>
#include <math.h>

#define NP 768
#define DD 128
#define NH 8
#define AA 312
#define KSPLIT 4
#define KCHUNK (NP / KSPLIT)   // 192

typedef unsigned long long u64;

// ---------------- f32x2 packed helpers (B300 FFMA2 path, PTX-only) ----------------
__device__ __forceinline__ u64 ffma2(u64 a, u64 b, u64 c) {
    u64 d; asm("fma.rn.f32x2 %0, %1, %2, %3;" : "=l"(d) : "l"(a), "l"(b), "l"(c)); return d;
}
__device__ __forceinline__ u64 fmul2(u64 a, u64 b) {
    u64 d; asm("mul.rn.f32x2 %0, %1, %2;" : "=l"(d) : "l"(a), "l"(b)); return d;
}
__device__ __forceinline__ u64 fadd2(u64 a, u64 b) {
    u64 d; asm("add.rn.f32x2 %0, %1, %2;" : "=l"(d) : "l"(a), "l"(b)); return d;
}
__device__ __forceinline__ float hsum2(u64 v) {
    float x, y; asm("mov.b64 {%0,%1}, %2;" : "=f"(x), "=f"(y) : "l"(v)); return x + y;
}

// ---------------- scratch (device globals, no allocation) ----------------
__device__ float g_ve[NP * NP];
__device__ float g_se[NP * NP];
__device__ float g_p4[KSPLIT * NP * DD];
__device__ float g_t4[KSPLIT * NP * DD];
__device__ float g_nrm[2 * NP];
__device__ float g_ah[NP * NH];

// ------------- row L2 norms for BOTH modalities, 8 rows/block -------------
__global__ void rownorm_both_k(const float* __restrict__ V, const float* __restrict__ Aat,
                               float* __restrict__ out) {
    int gr = blockIdx.x * 8 + (threadIdx.x >> 5);   // 0..1535
    int lane = threadIdx.x & 31;
    const float* x; int cols;
    if (gr < NP) { x = V + (size_t)gr * DD; cols = DD; }
    else         { x = Aat + (size_t)(gr - NP) * AA; cols = AA; }
    float s = 0.f;
    for (int c = lane; c < cols; c += 32) { float v = x[c]; s += v * v; }
    #pragma unroll
    for (int o = 16; o; o >>= 1) s += __shfl_down_sync(0xffffffffu, s, o);
    if (lane == 0) out[gr] = sqrtf(s);
}

// ------ cosine-sim GEMMs for BOTH modalities in one launch (z picks modality) ------
__global__ void __launch_bounds__(256, 2)
sim_both_kernel(const float* __restrict__ V, const float* __restrict__ Aat,
                const float* __restrict__ nrm,
                float* __restrict__ CV, float* __restrict__ CS, float invtemp) {
    __shared__ float As[32][34];
    __shared__ float Bs[32][34];
    const float* X; int K; const float* nr; float* C;
    if (blockIdx.z == 0) { X = V;  K = DD; nr = nrm;       C = CV; }
    else                 { X = Aat; K = AA; nr = nrm + NP; C = CS; }
    int i0 = blockIdx.y * 32, j0 = blockIdx.x * 32;
    int tx = threadIdx.x, ty = threadIdx.y;          // 16x16
    int t = ty * 16 + tx;
    u64 acc[2][2] = {{0ull,0ull},{0ull,0ull}};
    for (int k0 = 0; k0 < K; k0 += 32) {
        #pragma unroll
        for (int e = 0; e < 4; e++) {
            int idx = t + e * 256;
            int r = idx >> 5, c = idx & 31;
            int kk = k0 + c;
            float av = 0.f, bv = 0.f;
            if (kk < K) {
                av = X[(size_t)(i0 + r) * K + kk];
                bv = X[(size_t)(j0 + r) * K + kk];
            }
            As[r][c] = av;
            Bs[r][c] = bv;
        }
        __syncthreads();
        #pragma unroll
        for (int kk = 0; kk < 32; kk += 2) {
            u64 a0 = *(const u64*)&As[ty][kk];
            u64 a1 = *(const u64*)&As[ty + 16][kk];
            u64 b0 = *(const u64*)&Bs[tx][kk];
            u64 b1 = *(const u64*)&Bs[tx + 16][kk];
            acc[0][0] = ffma2(a0, b0, acc[0][0]);
            acc[0][1] = ffma2(a0, b1, acc[0][1]);
            acc[1][0] = ffma2(a1, b0, acc[1][0]);
            acc[1][1] = ffma2(a1, b1, acc[1][1]);
        }
        __syncthreads();
    }
    #pragma unroll
    for (int a = 0; a < 2; a++) {
        int i = i0 + ty + a * 16;
        float ni = nr[i];
        #pragma unroll
        for (int b = 0; b < 2; b++) {
            int j = j0 + tx + b * 16;
            float den = fmaxf(ni * nr[j], 1e-8f);
            C[(size_t)i * NP + j] = hsum2(acc[a][b]) / den * invtemp;
        }
    }
}

// ---------------- row softmax, in place; handles one or two matrices ----------------
__global__ void softmax_kernel(float* __restrict__ M1, float* __restrict__ M2) {
    __shared__ float buf[NP];
    __shared__ float red[8];
    int row = blockIdx.x;
    float* p = (row < NP) ? (M1 + (size_t)row * NP) : (M2 + (size_t)(row - NP) * NP);
    int t = threadIdx.x;                     // 256
    int wid = t >> 5, lane = t & 31;
    float mx = -1e30f;
    for (int c = t; c < NP; c += 256) { float v = p[c]; buf[c] = v; mx = fmaxf(mx, v); }
    #pragma unroll
    for (int o = 16; o; o >>= 1) mx = fmaxf(mx, __shfl_down_sync(0xffffffffu, mx, o));
    if (lane == 0) red[wid] = mx;
    __syncthreads();
    mx = red[0];
    #pragma unroll
    for (int w = 1; w < 8; w++) mx = fmaxf(mx, red[w]);
    float sum = 0.f;
    for (int c = t; c < NP; c += 256) { float e = expf(buf[c] - mx); buf[c] = e; sum += e; }
    __syncthreads();
    #pragma unroll
    for (int o = 16; o; o >>= 1) sum += __shfl_down_sync(0xffffffffu, sum, o);
    if (lane == 0) red[wid] = sum;
    __syncthreads();
    sum = 0.f;
    #pragma unroll
    for (int w = 0; w < 8; w++) sum += red[w];
    float inv = 1.f / sum;
    for (int c = t; c < NP; c += 256) p[c] = buf[c] * inv;
}

// ------- split-K dual aggregation: partials of edge@proto and (edge+last)@proto -------
// grid (DD/32, NP/32, KSPLIT); chunk s reduces k in [s*KCHUNK, (s+1)*KCHUNK)
__global__ void __launch_bounds__(256, 2)
dualagg_kernel(const float* __restrict__ edge, const float* __restrict__ last,
               const float* __restrict__ proto,
               float* __restrict__ outp4, float* __restrict__ outt4) {
    __shared__ float E1[32][34];
    __shared__ float E2[32][34];
    __shared__ float Prt[32][34];          // transposed: [d][k]
    int i0 = blockIdx.y * 32, d0 = blockIdx.x * 32;
    int s = blockIdx.z;
    int kbeg = s * KCHUNK, kend = kbeg + KCHUNK;
    int tx = threadIdx.x, ty = threadIdx.y;
    int t = ty * 16 + tx;
    u64 ap[2][2] = {{0ull,0ull},{0ull,0ull}};
    u64 at[2][2] = {{0ull,0ull},{0ull,0ull}};
    for (int k0 = kbeg; k0 < kend; k0 += 32) {
        #pragma unroll
        for (int e = 0; e < 4; e++) {
            int idx = t + e * 256;
            int r = idx >> 5, c = idx & 31;
            E1[r][c] = edge[(size_t)(i0 + r) * NP + k0 + c];
            E2[r][c] = last[(size_t)(i0 + r) * NP + k0 + c];
            Prt[c][r] = proto[(size_t)(k0 + r) * DD + d0 + c];
        }
        __syncthreads();
        #pragma unroll
        for (int kk = 0; kk < 32; kk += 2) {
            u64 e10 = *(const u64*)&E1[ty][kk];
            u64 e11 = *(const u64*)&E1[ty + 16][kk];
            u64 f0  = *(const u64*)&E2[ty][kk];
            u64 f1  = *(const u64*)&E2[ty + 16][kk];
            u64 s0 = fadd2(e10, f0);
            u64 s1 = fadd2(e11, f1);
            u64 p0 = *(const u64*)&Prt[tx][kk];
            u64 p1 = *(const u64*)&Prt[tx + 16][kk];
            ap[0][0] = ffma2(e10, p0, ap[0][0]);
            ap[0][1] = ffma2(e10, p1, ap[0][1]);
            ap[1][0] = ffma2(e11, p0, ap[1][0]);
            ap[1][1] = ffma2(e11, p1, ap[1][1]);
            at[0][0] = ffma2(s0, p0, at[0][0]);
            at[0][1] = ffma2(s0, p1, at[0][1]);
            at[1][0] = ffma2(s1, p0, at[1][0]);
            at[1][1] = ffma2(s1, p1, at[1][1]);
        }
        __syncthreads();
    }
    size_t base = (size_t)s * NP * DD;
    #pragma unroll
    for (int a = 0; a < 2; a++) {
        int i = i0 + ty + a * 16;
        #pragma unroll
        for (int b = 0; b < 2; b++) {
            int d = d0 + tx + b * 16;
            outp4[base + (size_t)i * DD + d] = hsum2(ap[a][b]);
            outt4[base + (size_t)i * DD + d] = hsum2(at[a][b]);
        }
    }
}

// --- sums KSPLIT partials; out = relu(LN(t@W^T + b)*g + beta) + p ; fused ah ------
__global__ void linear_ln_kernel(const float* __restrict__ T4, const float* __restrict__ P4,
                                 const float* __restrict__ W, const float* __restrict__ bias,
                                 const float* __restrict__ gamma, const float* __restrict__ beta,
                                 const float* __restrict__ W1, float* __restrict__ A,
                                 float* __restrict__ out) {
    __shared__ float trow[DD];
    __shared__ float x2s[DD];
    __shared__ float red[4];
    int i = blockIdx.x, d = threadIdx.x;     // 128 threads = 4 warps
    int wid = d >> 5, lane = d & 31;
    size_t off = (size_t)i * DD + d;
    float tval = 0.f, pval = 0.f;
    #pragma unroll
    for (int ss = 0; ss < KSPLIT; ss++) {
        tval += T4[(size_t)ss * NP * DD + off];
        pval += P4[(size_t)ss * NP * DD + off];
    }
    trow[d] = tval;
    __syncthreads();
    const float* w = W + (size_t)d * DD;
    float acc = bias[d];
    #pragma unroll 8
    for (int k = 0; k < DD; k++) acc += trow[k] * w[k];
    float s = acc;
    #pragma unroll
    for (int o = 16; o; o >>= 1) s += __shfl_down_sync(0xffffffffu, s, o);
    if (lane == 0) red[wid] = s;
    __syncthreads();
    float m = (red[0] + red[1] + red[2] + red[3]) * (1.f / DD);
    __syncthreads();
    float dev = acc - m;
    float v = dev * dev;
    #pragma unroll
    for (int o = 16; o; o >>= 1) v += __shfl_down_sync(0xffffffffu, v, o);
    if (lane == 0) red[wid] = v;
    __syncthreads();
    float var = (red[0] + red[1] + red[2] + red[3]) * (1.f / DD);
    float y = dev * rsqrtf(var + 1e-5f) * gamma[d] + beta[d];
    float o_val = fmaxf(y, 0.f) + pval;
    out[off] = o_val;
    x2s[d] = o_val * o_val;
    __syncthreads();
    #pragma unroll
    for (int hh = 0; hh < 2; hh++) {
        int h = wid * 2 + hh;
        float sa = 0.f;
        #pragma unroll
        for (int q = 0; q < 4; q++) {
            int dd = lane + q * 32;
            sa += W1[h * DD + dd] * x2s[dd];
        }
        #pragma unroll
        for (int o = 16; o; o >>= 1) sa += __shfl_down_sync(0xffffffffu, sa, o);
        if (lane == 0) A[i * NH + h] = sa;
    }
}

// ---------------- fused edge-MLP, 32x32 tile, 2x2/thread, f32x2 math ----------------
__global__ void __launch_bounds__(256, 2)
edge_kernel(const float* __restrict__ Pm, const float* __restrict__ A,
            const float* __restrict__ W1, const float* __restrict__ b1,
            const float* __restrict__ W2, const float* __restrict__ b2,
            const float* __restrict__ last, float invtemp,
            float* __restrict__ out) {
    __shared__ float Pi[32][34];
    __shared__ float Pj[32][34];
    __shared__ float Ws[NH][34];
    int i0 = blockIdx.y * 32, j0 = blockIdx.x * 32;
    int tx = threadIdx.x, ty = threadIdx.y;   // 16x16
    int t = ty * 16 + tx;
    u64 c2[2][2][NH];
    #pragma unroll
    for (int a = 0; a < 2; a++)
        #pragma unroll
        for (int b = 0; b < 2; b++)
            #pragma unroll
            for (int h = 0; h < NH; h++) c2[a][b][h] = 0ull;
    for (int k0 = 0; k0 < DD; k0 += 32) {
        #pragma unroll
        for (int e = 0; e < 4; e++) {
            int idx = t + e * 256;
            int r = idx >> 5, cc = idx & 31;
            Pi[r][cc] = Pm[(size_t)(i0 + r) * DD + k0 + cc];
            Pj[r][cc] = Pm[(size_t)(j0 + r) * DD + k0 + cc];
        }
        Ws[t >> 5][t & 31] = W1[(t >> 5) * DD + k0 + (t & 31)];  // 256 = NH*32
        __syncthreads();
        #pragma unroll
        for (int kk = 0; kk < 32; kk += 2) {
            u64 pi0 = *(const u64*)&Pi[ty][kk];
            u64 pi1 = *(const u64*)&Pi[ty + 16][kk];
            u64 pj0 = *(const u64*)&Pj[tx][kk];
            u64 pj1 = *(const u64*)&Pj[tx + 16][kk];
            u64 wv[NH];
            #pragma unroll
            for (int h = 0; h < NH; h++) wv[h] = *(const u64*)&Ws[h][kk];
            u64 p00 = fmul2(pi0, pj0);
            u64 p01 = fmul2(pi0, pj1);
            u64 p10 = fmul2(pi1, pj0);
            u64 p11 = fmul2(pi1, pj1);
            #pragma unroll
            for (int h = 0; h < NH; h++) {
                c2[0][0][h] = ffma2(wv[h], p00, c2[0][0][h]);
                c2[0][1][h] = ffma2(wv[h], p01, c2[0][1][h]);
                c2[1][0][h] = ffma2(wv[h], p10, c2[1][0][h]);
                c2[1][1][h] = ffma2(wv[h], p11, c2[1][1][h]);
            }
        }
        __syncthreads();
    }
    float w2[NH], bb1[NH];
    #pragma unroll
    for (int h = 0; h < NH; h++) { w2[h] = W2[h]; bb1[h] = b1[h]; }
    float bb2 = b2[0];
    float Ai[2][NH], Aj[2][NH];
    #pragma unroll
    for (int h = 0; h < NH; h++) {
        Ai[0][h] = A[(i0 + ty) * NH + h];
        Ai[1][h] = A[(i0 + ty + 16) * NH + h];
        Aj[0][h] = A[(j0 + tx) * NH + h];
        Aj[1][h] = A[(j0 + tx + 16) * NH + h];
    }
    #pragma unroll
    for (int a = 0; a < 2; a++) {
        int i = i0 + ty + a * 16;
        #pragma unroll
        for (int b = 0; b < 2; b++) {
            int j = j0 + tx + b * 16;
            float hr[NH];
            float m = 0.f;
            #pragma unroll
            for (int h = 0; h < NH; h++) {
                hr[h] = Ai[a][h] + Aj[b][h] + bb1[h] - 2.f * hsum2(c2[a][b][h]);
                m += hr[h];
            }
            m *= (1.f / NH);
            float v = 0.f;
            #pragma unroll
            for (int h = 0; h < NH; h++) { float dd = hr[h] - m; v += dd * dd; }
            v *= (1.f / NH);
            float inv = rsqrtf(v + 1e-5f);
            float acc = bb2;
            #pragma unroll
            for (int h = 0; h < NH; h++) {
                float hn = (hr[h] - m) * inv;
                hn = fmaxf(hn, 0.f);
                acc += hn * w2[h];
            }
            float e = tanhf(acc);
            out[(size_t)i * NP + j] = e * (last[(size_t)i * NP + j] + 1e-8f) * invtemp;
        }
    }
}

// =========================================================================================
extern "C" void kernel_launch(void* const* d_in, const int* in_sizes, int n_in,
                              void* d_out, int out_size) {
    const float* visual   = (const float*)d_in[0];
    const float* semantic = (const float*)d_in[1];
    const float* attrib   = (const float*)d_in[2];
    const float* Wvn  = (const float*)d_in[3];
    const float* bvn  = (const float*)d_in[4];
    const float* gvn  = (const float*)d_in[5];
    const float* betavn = (const float*)d_in[6];
    const float* Wve1 = (const float*)d_in[7];
    const float* bve1 = (const float*)d_in[8];
    const float* Wve2 = (const float*)d_in[9];
    const float* bve2 = (const float*)d_in[10];
    const float* Wsn  = (const float*)d_in[11];
    const float* bsn  = (const float*)d_in[12];
    const float* gsn  = (const float*)d_in[13];
    const float* betasn = (const float*)d_in[14];
    const float* Wse1 = (const float*)d_in[15];
    const float* bse1 = (const float*)d_in[16];
    const float* Wse2 = (const float*)d_in[17];
    const float* bse2 = (const float*)d_in[18];

    float* out = (float*)d_out;
    float* vp  = out;
    float* sp  = out + NP * DD;
    float* ve2 = out + 2 * NP * DD;
    float* se2 = ve2 + NP * NP;

    float *ve, *se, *gp4, *gt4, *gn, *ga;
    cudaGetSymbolAddress((void**)&ve, g_ve);
    cudaGetSymbolAddress((void**)&se, g_se);
    cudaGetSymbolAddress((void**)&gp4, g_p4);
    cudaGetSymbolAddress((void**)&gt4, g_t4);
    cudaGetSymbolAddress((void**)&gn, g_nrm);
    cudaGetSymbolAddress((void**)&ga, g_ah);

    dim3 b16(16, 16);
    dim3 gNN(NP / 32, NP / 32);            // 24x24
    dim3 gSim(NP / 32, NP / 32, 2);        // both modalities
    dim3 gND(DD / 32, NP / 32, KSPLIT);    // 4x24x4 = 384 CTAs

    // ve, se = softmax(cos_sim(...)/0.1) — both modalities batched per launch
    rownorm_both_k<<<2 * NP / 8, 256>>>(visual, attrib, gn);
    sim_both_kernel<<<gSim, b16>>>(visual, attrib, gn, ve, se, 10.f);
    softmax_kernel<<<2 * NP, 256>>>(ve, se);

    // vp = node_update(visual, last=se, edge=ve)   [+ fused ah for ve2]
    dualagg_kernel<<<gND, b16>>>(ve, se, visual, gp4, gt4);
    linear_ln_kernel<<<NP, DD>>>(gt4, gp4, Wvn, bvn, gvn, betavn, Wve1, ga, vp);

    // ve2 = edge_update(vp, last=ve, temp=10)
    edge_kernel<<<gNN, b16>>>(vp, ga, Wve1, bve1, Wve2, bve2, ve, 0.1f, ve2);
    softmax_kernel<<<NP, 256>>>(ve2, ve2);

    // sp = node_update(semantic, last=ve2, edge=se)   [+ fused ah for se2]
    dualagg_kernel<<<gND, b16>>>(se, ve2, semantic, gp4, gt4);
    linear_ln_kernel<<<NP, DD>>>(gt4, gp4, Wsn, bsn, gsn, betasn, Wse1, ga, sp);

    // se2 = edge_update(sp, last=se, temp=10)
    edge_kernel<<<gNN, b16>>>(sp, ga, Wse1, bse1, Wse2, bse2, se, 0.1f, se2);
    softmax_kernel<<<NP, 256>>>(se2, se2);
}